// round 13
// baseline (speedup 1.0000x reference)
#include <cuda_runtime.h>
#include <cuda_fp16.h>
#include <math.h>
#include <stdint.h>

#define BATCH 128
#define WDIM  512
#define HDIM  512
#define WH    (WDIM * HDIM)
#define NOUT  1536
#define K2_SPLITS 16
#define HPARTS 8

// ---------------- scratch (device globals: allocation-free rule) -------------
__device__ __align__(16) float  g_hpart[HPARTS * BATCH * HDIM];
__device__ __align__(16) float  g_havg[BATCH * HDIM];
__device__ __align__(16) float  g_f[BATCH * HDIM];
__device__ __align__(16) float  g_o[BATCH * HDIM];
__device__ __align__(16) float  g_a[BATCH * HDIM];
__device__ __align__(16) float  g_fo[BATCH * NOUT];          // atomic-accumulated fo|a
__device__ __align__(16) float  g_red1[2 * BATCH * HDIM];
__device__ __align__(16) float  g_red2[2 * BATCH * HDIM];
__device__ __align__(16) __half g_h16[BATCH * WH];
__device__ __align__(16) __half g_uw16[HDIM * HDIM];

// ---------------- fast math ------------------------------------------------------
__device__ __forceinline__ float fast_exp(float x)
{
    float y = x * 1.44269504089f;
    y = fminf(fmaxf(y, -125.0f), 125.0f);
    float z = y + 12582912.0f;
    int   n = __float_as_int(z) - 0x4B400000;
    float f = y - (z - 12582912.0f);
    float t = f * 0.69314718056f;
    float p = 0.0013888889f;
    p = fmaf(p, t, 0.0083333333f);
    p = fmaf(p, t, 0.0416666667f);
    p = fmaf(p, t, 0.1666666667f);
    p = fmaf(p, t, 0.5f);
    p = fmaf(p, t, 1.0f);
    p = fmaf(p, t, 1.0f);
    return __int_as_float(__float_as_int(p) + (n << 23));
}
__device__ __forceinline__ float fast_rcp(float d)
{
    float r = __int_as_float(0x7EF311C3 - __float_as_int(d));
    r = r * (2.0f - d * r);
    r = r * (2.0f - d * r);
    r = r * (2.0f - d * r);
    return r;
}
__device__ __forceinline__ float tanh_mufu(float x)
{
    float r;
    asm("tanh.approx.f32 %0, %1;" : "=f"(r) : "f"(x));
    return r;
}
__device__ __forceinline__ float ex2_mufu(float x)
{
    float r;
    asm("ex2.approx.f32 %0, %1;" : "=f"(r) : "f"(x));
    return r;
}

// ---------------- mma / ldmatrix / cp.async helpers ------------------------------
__device__ __forceinline__ void mma_f16(float* d, const uint32_t* a, const uint32_t* b)
{
    asm volatile(
        "mma.sync.aligned.m16n8k16.row.col.f32.f16.f16.f32 "
        "{%0,%1,%2,%3}, {%4,%5,%6,%7}, {%8,%9}, {%0,%1,%2,%3};"
        : "+f"(d[0]), "+f"(d[1]), "+f"(d[2]), "+f"(d[3])
        : "r"(a[0]), "r"(a[1]), "r"(a[2]), "r"(a[3]),
          "r"(b[0]), "r"(b[1]));
}
__device__ __forceinline__ void ldsm_x4(uint32_t* r, uint32_t addr)
{
    asm volatile("ldmatrix.sync.aligned.m8n8.x4.shared.b16 {%0,%1,%2,%3}, [%4];"
                 : "=r"(r[0]), "=r"(r[1]), "=r"(r[2]), "=r"(r[3]) : "r"(addr));
}
__device__ __forceinline__ void cp16(uint32_t saddr, const void* g)
{
    asm volatile("cp.async.cg.shared.global [%0], [%1], 16;" :: "r"(saddr), "l"(g));
}
__device__ __forceinline__ void cp_commit()
{
    asm volatile("cp.async.commit_group;" ::: "memory");
}
template<int N> __device__ __forceinline__ void cp_wait()
{
    asm volatile("cp.async.wait_group %0;" :: "n"(N) : "memory");
}

// ---------------- K0: h -> fp16 + partial W sums; u_w -> fp16; zero g_fo ----------
__global__ void k_prep(const float* __restrict__ h, const float* __restrict__ u_w)
{
    int gb  = blockIdx.x;
    int tid = threadIdx.x;
    if (gb < 512) {
        int b  = gb >> 2;
        int ws = gb & 3;                  // 128-row slice
        int tq = tid & 127;               // float4 column
        int th = tid >> 7;                // 0/1 -> 64-row half
        const float4* p = (const float4*)(h + (size_t)b * WH +
                                          ((size_t)ws * 128 + th * 64) * HDIM) + tq;
        uint2* q = (uint2*)(g_h16 + (size_t)b * WH +
                            ((size_t)ws * 128 + th * 64) * HDIM) + tq;
        float4 s = make_float4(0.f, 0.f, 0.f, 0.f);
#pragma unroll 8
        for (int w = 0; w < 64; ++w) {
            float4 v = p[(size_t)w * (HDIM / 4)];
            s.x += v.x; s.y += v.y; s.z += v.z; s.w += v.w;
            __half2 h0 = __floats2half2_rn(v.x, v.y);
            __half2 h1 = __floats2half2_rn(v.z, v.w);
            uint2 uu;
            uu.x = *reinterpret_cast<const uint32_t*>(&h0);
            uu.y = *reinterpret_cast<const uint32_t*>(&h1);
            q[(size_t)w * (HDIM / 4)] = uu;
        }
        int ws2 = ws * 2 + th;            // 8 partials of 64 rows each
        *(float4*)&g_hpart[(ws2 * BATCH + b) * HDIM + tq * 4] = s;
    } else if (gb < 544) {
        int t = (gb - 512) * 256 + tid;          // 0..8191
#pragma unroll
        for (int i = 0; i < 8; ++i) {
            int idx = t + i * 8192;              // float4 index, 65536 total
            float4 v = ((const float4*)u_w)[idx];
            ((__half2*)g_uw16)[idx * 2]     = __floats2half2_rn(v.x, v.y);
            ((__half2*)g_uw16)[idx * 2 + 1] = __floats2half2_rn(v.z, v.w);
        }
    } else {
        // zero g_fo: 49152 float4, 64 blocks x 256 threads x 3
        int t = (gb - 544) * 256 + tid;          // 0..16383
#pragma unroll
        for (int i = 0; i < 3; ++i)
            ((float4*)g_fo)[t + i * 16384] = make_float4(0.f, 0.f, 0.f, 0.f);
    }
}

// ---------------- K0b: merge h_avg partials --------------------------------------
__global__ void k_merge()
{
    int idx = blockIdx.x * blockDim.x + threadIdx.x;   // 0..16383 float4
    float4 s = make_float4(0.f, 0.f, 0.f, 0.f);
#pragma unroll
    for (int p = 0; p < HPARTS; ++p) {
        float4 v = ((const float4*)g_hpart)[p * (BATCH * HDIM / 4) + idx];
        s.x += v.x; s.y += v.y; s.z += v.z; s.w += v.w;
    }
    const float inv = 1.0f / 512.0f;
    ((float4*)g_havg)[idx] = make_float4(s.x * inv, s.y * inv, s.z * inv, s.w * inv);
}

// ---------------- K2: split-K fp32 GEMM for [fo | a], atomic reduction ------------
__global__ void __launch_bounds__(256)
k_fo(const float* __restrict__ g, const float* __restrict__ W_w,
     const float* __restrict__ U_w, const float* __restrict__ w_w)
{
    __shared__ __align__(16) float As[16 * 132];
    __shared__ __align__(16) float Bs[16 * 132];

    int nt  = blockIdx.x;
    int ks  = blockIdx.y;
    int tid = threadIdx.x;
    int tx  = tid & 15;
    int ty  = tid >> 4;

    float acc[8][8];
#pragma unroll
    for (int r = 0; r < 8; ++r)
#pragma unroll
        for (int s = 0; s < 8; ++s) acc[r][s] = 0.f;

    const int kbase = ks * 64;
    const int q  = tid & 3;
    const int lr = tid >> 2;

    for (int kk = 0; kk < 64; kk += 16) {
#pragma unroll
        for (int p = 0; p < 2; ++p) {
            int b  = p * 64 + lr;
            int kg = kbase + kk + q * 4;
            float4 v;
            if (kg < 512) v = *(const float4*)(g + b * 512 + kg);
            else          v = *(const float4*)(&g_havg[b * 512 + (kg - 512)]);
            float* dst = &As[(q * 4) * 132 + b];
            dst[0] = v.x; dst[132] = v.y; dst[2*132] = v.z; dst[3*132] = v.w;
        }
#pragma unroll
        for (int p = 0; p < 2; ++p) {
            int jj = p * 64 + lr;
            int j  = nt * 128 + jj;
            int kg = kbase + kk + q * 4;
            float4 v;
            if (j < 1024) {
                if (kg < 512) v = *(const float4*)(W_w + j * 512 + kg);
                else          v = *(const float4*)(U_w + j * 512 + (kg - 512));
            } else {
                if (kg < 512) v = *(const float4*)(w_w + (j - 1024) * 512 + kg);
                else          v = make_float4(0.f, 0.f, 0.f, 0.f);
            }
            float* dst = &Bs[(q * 4) * 132 + jj];
            dst[0] = v.x; dst[132] = v.y; dst[2*132] = v.z; dst[3*132] = v.w;
        }
        __syncthreads();

#pragma unroll
        for (int kc = 0; kc < 16; ++kc) {
            float4 a0 = *(const float4*)&As[kc * 132 + ty * 8];
            float4 a1 = *(const float4*)&As[kc * 132 + ty * 8 + 4];
            float4 b0 = *(const float4*)&Bs[kc * 132 + tx * 8];
            float4 b1 = *(const float4*)&Bs[kc * 132 + tx * 8 + 4];
            float av[8] = {a0.x, a0.y, a0.z, a0.w, a1.x, a1.y, a1.z, a1.w};
            float bv[8] = {b0.x, b0.y, b0.z, b0.w, b1.x, b1.y, b1.z, b1.w};
#pragma unroll
            for (int r = 0; r < 8; ++r)
#pragma unroll
                for (int s = 0; s < 8; ++s) acc[r][s] += av[r] * bv[s];
        }
        __syncthreads();
    }

    // atomic reduction into g_fo (no g_part round-trip)
#pragma unroll
    for (int r = 0; r < 8; ++r) {
        int bb = ty * 8 + r;
        float* dst = &g_fo[bb * NOUT + nt * 128 + tx * 8];
#pragma unroll
        for (int s = 0; s < 8; ++s)
            atomicAdd(dst + s, acc[r][s]);
    }
}

// ---------------- K2b: activation over accumulated g_fo ---------------------------
__global__ void k_fo_fin(const float* __restrict__ U_b)
{
    int idx = blockIdx.x * blockDim.x + threadIdx.x;   // 0..49151 (j quads)
    int b  = idx / (NOUT / 4);
    int j4 = idx - b * (NOUT / 4);
    int j  = j4 * 4;
    float4 s = *(const float4*)&g_fo[b * NOUT + j];
    if (j < 1024) {
        float4 ub = *(const float4*)&U_b[j];
        s.x = fast_rcp(1.f + fast_exp(-(s.x + ub.x)));
        s.y = fast_rcp(1.f + fast_exp(-(s.y + ub.y)));
        s.z = fast_rcp(1.f + fast_exp(-(s.z + ub.z)));
        s.w = fast_rcp(1.f + fast_exp(-(s.w + ub.w)));
        if (j < 512) *(float4*)&g_f[b * 512 + j]         = s;
        else         *(float4*)&g_o[b * 512 + (j - 512)] = s;
    } else {
        *(float4*)&g_a[b * 512 + (j - 1024)] = s;
    }
}

// ---------------- K3: fp16 mma (R8 proven config, ex2 epilogue) -------------------
// CTA = (64-col H tile, 256-row W slice, batch). 256 threads, 8 warps, 2 CTAs/SM.
#define KCH     64
#define NCHUNK  8
#define OFF_ADD_F  0               // 64 floats
#define OFF_R1_F   64
#define OFF_R2_F   576
#define SM_STAGE_B 4608            // stages: A 32KB + B 8KB, x2
#define A_BYTES    32768
#define STAGE_BYTES 40960
#define S2_STRIDE  33
#define K3_SMEM_BYTES (SM_STAGE_B + 2 * STAGE_BYTES)   // 86528

__global__ void __launch_bounds__(256, 2)
k_main(const float* __restrict__ c, const float* __restrict__ u_b)
{
    extern __shared__ __align__(128) float sm[];
    const uint32_t smb = (uint32_t)__cvta_generic_to_shared(sm);

    const int ht0  = blockIdx.x * 64;
    const int ws   = blockIdx.y;      // 0/1 : 256-row W slice
    const int b    = blockIdx.z;
    const int tid  = threadIdx.x;
    const int wid  = tid >> 5;
    const int lane = tid & 31;
    const int wm   = wid >> 1;        // 0..3
    const int wn   = wid & 1;         // 0..1
    const int g4   = lane >> 2;
    const int t4   = lane & 3;

    const __half* hbs = g_h16 + (size_t)b * WH + (size_t)ws * 256 * HDIM;

    if (tid < 64)
        sm[OFF_ADD_F + tid] = g_a[b * HDIM + ht0 + tid] + u_b[ht0 + tid];

    // ---- cp.async staging ----
    const int crow = tid >> 3;        // 0..31
    const int aq   = tid & 7;
    const int brow = tid >> 2;        // 0..63
    const int bq0  = (tid & 3) * 2;

    auto load_chunk = [&](int ch, int st) {
        const uint32_t sa = smb + SM_STAGE_B + (uint32_t)st * STAGE_BYTES;
        const __half* gA = hbs + ch * KCH + aq * 8;
#pragma unroll
        for (int p = 0; p < 8; ++p) {
            int row = crow + p * 32;
            cp16(sa + (uint32_t)(row * 128 + ((aq ^ (row & 7)) << 4)),
                 gA + (size_t)row * HDIM);
        }
        const uint32_t sb = sa + A_BYTES;
        const __half* gB = g_uw16 + (size_t)(ht0 + brow) * HDIM + ch * KCH;
#pragma unroll
        for (int i = 0; i < 2; ++i) {
            int q = bq0 + i;
            cp16(sb + (uint32_t)(brow * 128 + ((q ^ (brow & 7)) << 4)), gB + q * 8);
        }
        cp_commit();
    };

    // ---- ldmatrix per-lane bases ----
    const int lane15 = lane & 15;
    const int laneQA = lane >> 4;
    const int laneQB = (lane >> 3) & 1;

    uint32_t aBase[4], aRL[4];
#pragma unroll
    for (int tm = 0; tm < 4; ++tm) {
        int row = wm * 64 + tm * 16 + lane15;
        aRL[tm]   = row & 7;
        aBase[tm] = smb + SM_STAGE_B + (uint32_t)(row * 128);
    }
    uint32_t bBase[2], bRL[2];
#pragma unroll
    for (int p = 0; p < 2; ++p) {
        int row = wn * 32 + p * 16 + ((lane >> 4) << 3) + (lane & 7);
        bRL[p]   = row & 7;
        bBase[p] = smb + SM_STAGE_B + A_BYTES + (uint32_t)(row * 128);
    }

    float acc[4][4][4];
#pragma unroll
    for (int i = 0; i < 4; ++i)
#pragma unroll
        for (int j = 0; j < 4; ++j)
#pragma unroll
            for (int r = 0; r < 4; ++r) acc[i][j][r] = 0.f;

    // ---- 2-stage pipeline (R8 proven config) ----
    load_chunk(0, 0);
    load_chunk(1, 1);

    for (int ch = 0; ch < NCHUNK; ++ch) {
        const int st = ch & 1;
        if (ch == NCHUNK - 1) cp_wait<0>(); else cp_wait<1>();
        __syncthreads();

        const uint32_t off = (uint32_t)st * STAGE_BYTES;
#pragma unroll
        for (int ks = 0; ks < 4; ++ks) {
            const uint32_t qb = (uint32_t)(ks * 2);
            uint32_t af[4][4], bf[4][2];
#pragma unroll
            for (int tm = 0; tm < 4; ++tm)
                ldsm_x4(af[tm], aBase[tm] + off + (((qb + laneQA) ^ aRL[tm]) << 4));
#pragma unroll
            for (int p = 0; p < 2; ++p) {
                uint32_t tmp[4];
                ldsm_x4(tmp, bBase[p] + off + (((qb + laneQB) ^ bRL[p]) << 4));
                bf[2 * p][0] = tmp[0];     bf[2 * p][1] = tmp[1];
                bf[2 * p + 1][0] = tmp[2]; bf[2 * p + 1][1] = tmp[3];
            }
#pragma unroll
            for (int tm = 0; tm < 4; ++tm)
#pragma unroll
                for (int tn = 0; tn < 4; ++tn)
                    mma_f16(acc[tm][tn], af[tm], bf[tn]);
        }
        __syncthreads();
        if (ch + 2 < NCHUNK) load_chunk(ch + 2, st);
    }

    // ---- epilogue: exp(sigmoid(x)) ∝ exp2(K*tanh(x/2)); sqrt(e) cancels ----------
    __half2* S2 = (__half2*)(sm + SM_STAGE_B / 4);   // 256 x 33 half2, aliases stages
    const float KE = 0.72134752f;     // 0.5 * log2(e)
#pragma unroll
    for (int tm = 0; tm < 4; ++tm) {
#pragma unroll
        for (int tn = 0; tn < 4; ++tn) {
            int colb = wn * 32 + tn * 8 + t4 * 2;
            float add0 = sm[OFF_ADD_F + colb];
            float add1 = sm[OFF_ADD_F + colb + 1];
#pragma unroll
            for (int r = 0; r < 2; ++r) {
                int w = wm * 64 + tm * 16 + g4 + r * 8;
                float x0 = acc[tm][tn][r * 2 + 0] + add0;
                float x1 = acc[tm][tn][r * 2 + 1] + add1;
                float s0 = ex2_mufu(KE * tanh_mufu(0.5f * x0));
                float s1 = ex2_mufu(KE * tanh_mufu(0.5f * x1));
                S2[w * S2_STRIDE + (colb >> 1)] = __floats2half2_rn(s0, s1);
            }
        }
    }
    __syncthreads();

    // ---- partial softmax denominator + weighted-c numerator over 256 rows --------
    const int colp = tid & 31;
    const int seg  = tid >> 5;        // 8 segments x 32 w
    const float* cbase = c + (size_t)b * WH + (size_t)ws * 256 * HDIM
                       + ht0 + colp * 2;
    float dsx = 0.f, dsy = 0.f, wsx = 0.f, wsy = 0.f;
#pragma unroll 4
    for (int ww = 0; ww < 32; ++ww) {
        int w = seg * 32 + ww;
        float2 e  = __half22float2(S2[w * S2_STRIDE + colp]);
        float2 cv = __ldcg((const float2*)(cbase + (size_t)w * HDIM));
        dsx += e.x; dsy += e.y;
        wsx += e.x * cv.x; wsy += e.y * cv.y;
    }
    __syncthreads();
    *(float2*)&sm[OFF_R1_F + seg * 64 + colp * 2] = make_float2(dsx, dsy);
    *(float2*)&sm[OFF_R2_F + seg * 64 + colp * 2] = make_float2(wsx, wsy);
    __syncthreads();

    if (tid < 64) {
        float dt = 0.f, wt = 0.f;
#pragma unroll
        for (int s2 = 0; s2 < 8; ++s2) {
            dt += sm[OFF_R1_F + s2 * 64 + tid];
            wt += sm[OFF_R2_F + s2 * 64 + tid];
        }
        int gi = (ws * BATCH + b) * HDIM + ht0 + tid;
        g_red1[gi] = dt;
        g_red2[gi] = wt;
    }
}

// ---------------- K4: combine partials -> outputs ---------------------------------
__global__ void k_comb(const float* __restrict__ c_g, float* __restrict__ out)
{
    int idx = blockIdx.x * blockDim.x + threadIdx.x;
    float dt = g_red1[idx] + g_red1[BATCH * HDIM + idx];
    float wt = g_red2[idx] + g_red2[BATCH * HDIM + idx];
    float newc = g_f[idx] * c_g[idx] + wt / dt;
    out[BATCH * HDIM + idx] = newc;            // new_c
    out[idx] = g_o[idx] * tanhf(newc);         // new_g
}

// ---------------- launch -----------------------------------------------------------
extern "C" void kernel_launch(void* const* d_in, const int* in_sizes, int n_in,
                              void* d_out, int out_size)
{
    const float* g   = (const float*)d_in[0];
    const float* c_g = (const float*)d_in[1];
    const float* h   = (const float*)d_in[2];
    const float* c   = (const float*)d_in[3];
    const float* W_w = (const float*)d_in[4];
    const float* w_w = (const float*)d_in[5];
    const float* U_w = (const float*)d_in[6];
    const float* U_b = (const float*)d_in[7];
    const float* u_w = (const float*)d_in[8];
    const float* u_b = (const float*)d_in[9];
    float* out = (float*)d_out;

    (void)in_sizes; (void)n_in; (void)out_size;

    k_prep<<<608, 256>>>(h, u_w);          // 512 h-blocks + 32 u_w + 64 zero g_fo
    k_merge<<<64, 256>>>();
    k_fo<<<dim3(12, 16), 256>>>(g, W_w, U_w, w_w);
    k_fo_fin<<<192, 256>>>(U_b);

    static int smem_set = 0;
    if (!smem_set) {
        cudaFuncSetAttribute(k_main, cudaFuncAttributeMaxDynamicSharedMemorySize,
                             K3_SMEM_BYTES);
        smem_set = 1;
    }
    k_main<<<dim3(8, 2, 128), 256, K3_SMEM_BYTES>>>(c, u_b);
    k_comb<<<256, 256>>>(c_g, out);
}

// round 14
// speedup vs baseline: 1.0770x; 1.0770x over previous
#include <cuda_runtime.h>
#include <cuda_fp16.h>
#include <math.h>
#include <stdint.h>

#define BATCH 128
#define WDIM  512
#define HDIM  512
#define WH    (WDIM * HDIM)
#define NOUT  1536
#define K2_SPLITS 16
#define HPARTS 8

// ---------------- scratch (device globals: allocation-free rule) -------------
__device__ __align__(16) float  g_hpart[HPARTS * BATCH * HDIM];
__device__ __align__(16) float  g_part[K2_SPLITS * BATCH * NOUT];
__device__ __align__(16) float  g_red1[2 * BATCH * HDIM];
__device__ __align__(16) float  g_red2[2 * BATCH * HDIM];
__device__ __align__(16) __half g_h16[BATCH * WH];
__device__ __align__(16) __half g_uw16[HDIM * HDIM];

// ---------------- fast math ------------------------------------------------------
__device__ __forceinline__ float fast_exp(float x)
{
    float y = x * 1.44269504089f;
    y = fminf(fmaxf(y, -125.0f), 125.0f);
    float z = y + 12582912.0f;
    int   n = __float_as_int(z) - 0x4B400000;
    float f = y - (z - 12582912.0f);
    float t = f * 0.69314718056f;
    float p = 0.0013888889f;
    p = fmaf(p, t, 0.0083333333f);
    p = fmaf(p, t, 0.0416666667f);
    p = fmaf(p, t, 0.1666666667f);
    p = fmaf(p, t, 0.5f);
    p = fmaf(p, t, 1.0f);
    p = fmaf(p, t, 1.0f);
    return __int_as_float(__float_as_int(p) + (n << 23));
}
__device__ __forceinline__ float fast_rcp(float d)
{
    float r = __int_as_float(0x7EF311C3 - __float_as_int(d));
    r = r * (2.0f - d * r);
    r = r * (2.0f - d * r);
    r = r * (2.0f - d * r);
    return r;
}
__device__ __forceinline__ float tanh_mufu(float x)
{
    float r;
    asm("tanh.approx.f32 %0, %1;" : "=f"(r) : "f"(x));
    return r;
}
__device__ __forceinline__ float ex2_mufu(float x)
{
    float r;
    asm("ex2.approx.f32 %0, %1;" : "=f"(r) : "f"(x));
    return r;
}

// ---------------- mma / ldmatrix / cp.async helpers ------------------------------
__device__ __forceinline__ void mma_f16(float* d, const uint32_t* a, const uint32_t* b)
{
    asm volatile(
        "mma.sync.aligned.m16n8k16.row.col.f32.f16.f16.f32 "
        "{%0,%1,%2,%3}, {%4,%5,%6,%7}, {%8,%9}, {%0,%1,%2,%3};"
        : "+f"(d[0]), "+f"(d[1]), "+f"(d[2]), "+f"(d[3])
        : "r"(a[0]), "r"(a[1]), "r"(a[2]), "r"(a[3]),
          "r"(b[0]), "r"(b[1]));
}
__device__ __forceinline__ void ldsm_x4(uint32_t* r, uint32_t addr)
{
    asm volatile("ldmatrix.sync.aligned.m8n8.x4.shared.b16 {%0,%1,%2,%3}, [%4];"
                 : "=r"(r[0]), "=r"(r[1]), "=r"(r[2]), "=r"(r[3]) : "r"(addr));
}
__device__ __forceinline__ void cp16(uint32_t saddr, const void* g)
{
    asm volatile("cp.async.cg.shared.global [%0], [%1], 16;" :: "r"(saddr), "l"(g));
}
__device__ __forceinline__ void cp_commit()
{
    asm volatile("cp.async.commit_group;" ::: "memory");
}
template<int N> __device__ __forceinline__ void cp_wait()
{
    asm volatile("cp.async.wait_group %0;" :: "n"(N) : "memory");
}

// ---------------- K0: h -> fp16 + partial W sums (float4 loads); u_w -> fp16 ------
__global__ void k_prep(const float* __restrict__ h, const float* __restrict__ u_w)
{
    int gb  = blockIdx.x;
    int tid = threadIdx.x;
    if (gb < 512) {
        int b  = gb >> 2;
        int ws = gb & 3;                  // 128-row slice
        int tq = tid & 127;               // float4 column
        int th = tid >> 7;                // 0/1 -> 64-row half
        const float4* p = (const float4*)(h + (size_t)b * WH +
                                          ((size_t)ws * 128 + th * 64) * HDIM) + tq;
        uint2* q = (uint2*)(g_h16 + (size_t)b * WH +
                            ((size_t)ws * 128 + th * 64) * HDIM) + tq;
        float4 s = make_float4(0.f, 0.f, 0.f, 0.f);
#pragma unroll 8
        for (int w = 0; w < 64; ++w) {
            float4 v = p[(size_t)w * (HDIM / 4)];
            s.x += v.x; s.y += v.y; s.z += v.z; s.w += v.w;
            __half2 h0 = __floats2half2_rn(v.x, v.y);
            __half2 h1 = __floats2half2_rn(v.z, v.w);
            uint2 uu;
            uu.x = *reinterpret_cast<const uint32_t*>(&h0);
            uu.y = *reinterpret_cast<const uint32_t*>(&h1);
            q[(size_t)w * (HDIM / 4)] = uu;
        }
        int ws2 = ws * 2 + th;            // 8 partials of 64 rows each
        *(float4*)&g_hpart[(ws2 * BATCH + b) * HDIM + tq * 4] = s;
    } else {
        int t = (gb - 512) * 256 + tid;          // 0..8191
#pragma unroll
        for (int i = 0; i < 8; ++i) {
            int idx = t + i * 8192;              // float4 index, 65536 total
            float4 v = ((const float4*)u_w)[idx];
            ((__half2*)g_uw16)[idx * 2]     = __floats2half2_rn(v.x, v.y);
            ((__half2*)g_uw16)[idx * 2 + 1] = __floats2half2_rn(v.z, v.w);
        }
    }
}

// ---------------- K2: split-K fp32 GEMM for [fo | a] (R12 proven) ------------------
__global__ void __launch_bounds__(256)
k_fo(const float* __restrict__ g, const float* __restrict__ W_w,
     const float* __restrict__ U_w, const float* __restrict__ w_w)
{
    __shared__ __align__(16) float As[16 * 132];
    __shared__ __align__(16) float Bs[16 * 132];

    int nt  = blockIdx.x;
    int ks  = blockIdx.y;
    int tid = threadIdx.x;
    int tx  = tid & 15;
    int ty  = tid >> 4;

    float acc[8][8];
#pragma unroll
    for (int r = 0; r < 8; ++r)
#pragma unroll
        for (int s = 0; s < 8; ++s) acc[r][s] = 0.f;

    const int kbase = ks * 64;
    const int q  = tid & 3;
    const int lr = tid >> 2;

    for (int kk = 0; kk < 64; kk += 16) {
#pragma unroll
        for (int p = 0; p < 2; ++p) {
            int b  = p * 64 + lr;
            int kg = kbase + kk + q * 4;
            float4 v;
            if (kg < 512) {
                v = *(const float4*)(g + b * 512 + kg);
            } else {
                float4 a4 = make_float4(0.f, 0.f, 0.f, 0.f);
#pragma unroll
                for (int s = 0; s < HPARTS; ++s) {
                    float4 t = *(const float4*)&g_hpart[(s * BATCH + b) * HDIM +
                                                        (kg - 512)];
                    a4.x += t.x; a4.y += t.y; a4.z += t.z; a4.w += t.w;
                }
                const float inv = 1.0f / 512.0f;
                v = make_float4(a4.x * inv, a4.y * inv, a4.z * inv, a4.w * inv);
            }
            float* dst = &As[(q * 4) * 132 + b];
            dst[0] = v.x; dst[132] = v.y; dst[2*132] = v.z; dst[3*132] = v.w;
        }
#pragma unroll
        for (int p = 0; p < 2; ++p) {
            int jj = p * 64 + lr;
            int j  = nt * 128 + jj;
            int kg = kbase + kk + q * 4;
            float4 v;
            if (j < 1024) {
                if (kg < 512) v = *(const float4*)(W_w + j * 512 + kg);
                else          v = *(const float4*)(U_w + j * 512 + (kg - 512));
            } else {
                if (kg < 512) v = *(const float4*)(w_w + (j - 1024) * 512 + kg);
                else          v = make_float4(0.f, 0.f, 0.f, 0.f);
            }
            float* dst = &Bs[(q * 4) * 132 + jj];
            dst[0] = v.x; dst[132] = v.y; dst[2*132] = v.z; dst[3*132] = v.w;
        }
        __syncthreads();

#pragma unroll
        for (int kc = 0; kc < 16; ++kc) {
            float4 a0 = *(const float4*)&As[kc * 132 + ty * 8];
            float4 a1 = *(const float4*)&As[kc * 132 + ty * 8 + 4];
            float4 b0 = *(const float4*)&Bs[kc * 132 + tx * 8];
            float4 b1 = *(const float4*)&Bs[kc * 132 + tx * 8 + 4];
            float av[8] = {a0.x, a0.y, a0.z, a0.w, a1.x, a1.y, a1.z, a1.w};
            float bv[8] = {b0.x, b0.y, b0.z, b0.w, b1.x, b1.y, b1.z, b1.w};
#pragma unroll
            for (int r = 0; r < 8; ++r)
#pragma unroll
                for (int s = 0; s < 8; ++s) acc[r][s] += av[r] * bv[s];
        }
        __syncthreads();
    }

#pragma unroll
    for (int r = 0; r < 8; ++r) {
        int bb = ty * 8 + r;
        float* dst = &g_part[(ks * 128 + bb) * NOUT + nt * 128 + tx * 8];
        *(float4*)dst       = make_float4(acc[r][0], acc[r][1], acc[r][2], acc[r][3]);
        *(float4*)(dst + 4) = make_float4(acc[r][4], acc[r][5], acc[r][6], acc[r][7]);
    }
}

// ---------------- K3: fp16 mma (R8 config); 'a' reduction fused into prologue -----
// CTA = (64-col H tile, 256-row W slice, batch). 256 threads, 8 warps, 2 CTAs/SM.
#define KCH     64
#define NCHUNK  8
#define OFF_ADD_F  0               // 64 floats
#define OFF_R1_F   64
#define OFF_R2_F   576
#define SM_STAGE_B 4608            // stages: A 32KB + B 8KB, x2
#define A_BYTES    32768
#define STAGE_BYTES 40960
#define S2_STRIDE  33
#define K3_SMEM_BYTES (SM_STAGE_B + 2 * STAGE_BYTES)   // 86528

__global__ void __launch_bounds__(256, 2)
k_main(const float* __restrict__ c, const float* __restrict__ u_b)
{
    extern __shared__ __align__(128) float sm[];
    const uint32_t smb = (uint32_t)__cvta_generic_to_shared(sm);

    const int ht0  = blockIdx.x * 64;
    const int ws   = blockIdx.y;      // 0/1 : 256-row W slice
    const int b    = blockIdx.z;
    const int tid  = threadIdx.x;
    const int wid  = tid >> 5;
    const int lane = tid & 31;
    const int wm   = wid >> 1;        // 0..3
    const int wn   = wid & 1;         // 0..1
    const int g4   = lane >> 2;
    const int t4   = lane & 3;

    const __half* hbs = g_h16 + (size_t)b * WH + (size_t)ws * 256 * HDIM;

    // fused 'a' reduction: a[col] = sum over K2 splits + u_b (consumed at epilogue)
    if (tid < 64) {
        float a = u_b[ht0 + tid];
#pragma unroll
        for (int ks = 0; ks < K2_SPLITS; ++ks)
            a += g_part[(ks * 128 + b) * NOUT + 1024 + ht0 + tid];
        sm[OFF_ADD_F + tid] = a;
    }

    // ---- cp.async staging ----
    const int crow = tid >> 3;        // 0..31
    const int aq   = tid & 7;
    const int brow = tid >> 2;        // 0..63
    const int bq0  = (tid & 3) * 2;

    auto load_chunk = [&](int ch, int st) {
        const uint32_t sa = smb + SM_STAGE_B + (uint32_t)st * STAGE_BYTES;
        const __half* gA = hbs + ch * KCH + aq * 8;
#pragma unroll
        for (int p = 0; p < 8; ++p) {
            int row = crow + p * 32;
            cp16(sa + (uint32_t)(row * 128 + ((aq ^ (row & 7)) << 4)),
                 gA + (size_t)row * HDIM);
        }
        const uint32_t sb = sa + A_BYTES;
        const __half* gB = g_uw16 + (size_t)(ht0 + brow) * HDIM + ch * KCH;
#pragma unroll
        for (int i = 0; i < 2; ++i) {
            int q = bq0 + i;
            cp16(sb + (uint32_t)(brow * 128 + ((q ^ (brow & 7)) << 4)), gB + q * 8);
        }
        cp_commit();
    };

    // ---- ldmatrix per-lane bases ----
    const int lane15 = lane & 15;
    const int laneQA = lane >> 4;
    const int laneQB = (lane >> 3) & 1;

    uint32_t aBase[4], aRL[4];
#pragma unroll
    for (int tm = 0; tm < 4; ++tm) {
        int row = wm * 64 + tm * 16 + lane15;
        aRL[tm]   = row & 7;
        aBase[tm] = smb + SM_STAGE_B + (uint32_t)(row * 128);
    }
    uint32_t bBase[2], bRL[2];
#pragma unroll
    for (int p = 0; p < 2; ++p) {
        int row = wn * 32 + p * 16 + ((lane >> 4) << 3) + (lane & 7);
        bRL[p]   = row & 7;
        bBase[p] = smb + SM_STAGE_B + A_BYTES + (uint32_t)(row * 128);
    }

    float acc[4][4][4];
#pragma unroll
    for (int i = 0; i < 4; ++i)
#pragma unroll
        for (int j = 0; j < 4; ++j)
#pragma unroll
            for (int r = 0; r < 4; ++r) acc[i][j][r] = 0.f;

    // ---- 2-stage pipeline (R8 proven config) ----
    load_chunk(0, 0);
    load_chunk(1, 1);

    for (int ch = 0; ch < NCHUNK; ++ch) {
        const int st = ch & 1;
        if (ch == NCHUNK - 1) cp_wait<0>(); else cp_wait<1>();
        __syncthreads();

        const uint32_t off = (uint32_t)st * STAGE_BYTES;
#pragma unroll
        for (int ks = 0; ks < 4; ++ks) {
            const uint32_t qb = (uint32_t)(ks * 2);
            uint32_t af[4][4], bf[4][2];
#pragma unroll
            for (int tm = 0; tm < 4; ++tm)
                ldsm_x4(af[tm], aBase[tm] + off + (((qb + laneQA) ^ aRL[tm]) << 4));
#pragma unroll
            for (int p = 0; p < 2; ++p) {
                uint32_t tmp[4];
                ldsm_x4(tmp, bBase[p] + off + (((qb + laneQB) ^ bRL[p]) << 4));
                bf[2 * p][0] = tmp[0];     bf[2 * p][1] = tmp[1];
                bf[2 * p + 1][0] = tmp[2]; bf[2 * p + 1][1] = tmp[3];
            }
#pragma unroll
            for (int tm = 0; tm < 4; ++tm)
#pragma unroll
                for (int tn = 0; tn < 4; ++tn)
                    mma_f16(acc[tm][tn], af[tm], bf[tn]);
        }
        __syncthreads();
        if (ch + 2 < NCHUNK) load_chunk(ch + 2, st);
    }

    // ---- epilogue: exp(sigmoid(x)) ∝ exp2(K*tanh(x/2)); sqrt(e) cancels ----------
    __half2* S2 = (__half2*)(sm + SM_STAGE_B / 4);   // 256 x 33 half2, aliases stages
    const float KE = 0.72134752f;     // 0.5 * log2(e)
#pragma unroll
    for (int tm = 0; tm < 4; ++tm) {
#pragma unroll
        for (int tn = 0; tn < 4; ++tn) {
            int colb = wn * 32 + tn * 8 + t4 * 2;
            float add0 = sm[OFF_ADD_F + colb];
            float add1 = sm[OFF_ADD_F + colb + 1];
#pragma unroll
            for (int r = 0; r < 2; ++r) {
                int w = wm * 64 + tm * 16 + g4 + r * 8;
                float x0 = acc[tm][tn][r * 2 + 0] + add0;
                float x1 = acc[tm][tn][r * 2 + 1] + add1;
                float s0 = ex2_mufu(KE * tanh_mufu(0.5f * x0));
                float s1 = ex2_mufu(KE * tanh_mufu(0.5f * x1));
                S2[w * S2_STRIDE + (colb >> 1)] = __floats2half2_rn(s0, s1);
            }
        }
    }
    __syncthreads();

    // ---- partial softmax denominator + weighted-c numerator over 256 rows --------
    const int colp = tid & 31;
    const int seg  = tid >> 5;        // 8 segments x 32 w
    const float* cbase = c + (size_t)b * WH + (size_t)ws * 256 * HDIM
                       + ht0 + colp * 2;
    float dsx = 0.f, dsy = 0.f, wsx = 0.f, wsy = 0.f;
#pragma unroll 4
    for (int ww = 0; ww < 32; ++ww) {
        int w = seg * 32 + ww;
        float2 e  = __half22float2(S2[w * S2_STRIDE + colp]);
        float2 cv = __ldcg((const float2*)(cbase + (size_t)w * HDIM));
        dsx += e.x; dsy += e.y;
        wsx += e.x * cv.x; wsy += e.y * cv.y;
    }
    __syncthreads();
    *(float2*)&sm[OFF_R1_F + seg * 64 + colp * 2] = make_float2(dsx, dsy);
    *(float2*)&sm[OFF_R2_F + seg * 64 + colp * 2] = make_float2(wsx, wsy);
    __syncthreads();

    if (tid < 64) {
        float dt = 0.f, wt = 0.f;
#pragma unroll
        for (int s2 = 0; s2 < 8; ++s2) {
            dt += sm[OFF_R1_F + s2 * 64 + tid];
            wt += sm[OFF_R2_F + s2 * 64 + tid];
        }
        int gi = (ws * BATCH + b) * HDIM + ht0 + tid;
        g_red1[gi] = dt;
        g_red2[gi] = wt;
    }
}

// ---------------- K4: combine partials + f/o sigmoid -> outputs -------------------
__global__ void k_comb(const float* __restrict__ U_b, const float* __restrict__ c_g,
                       float* __restrict__ out)
{
    int idx = blockIdx.x * blockDim.x + threadIdx.x;   // 0..65535 = b*512+j
    int b = idx >> 9;
    int j = idx & 511;

    float sf = 0.f, so = 0.f;
#pragma unroll
    for (int ks = 0; ks < K2_SPLITS; ++ks) {
        const float* row = &g_part[(ks * 128 + b) * NOUT];
        sf += row[j];
        so += row[j + 512];
    }
    float f = fast_rcp(1.f + fast_exp(-(sf + U_b[j])));
    float o = fast_rcp(1.f + fast_exp(-(so + U_b[j + 512])));

    float dt = g_red1[idx] + g_red1[BATCH * HDIM + idx];
    float wt = g_red2[idx] + g_red2[BATCH * HDIM + idx];
    float newc = f * c_g[idx] + wt / dt;
    out[BATCH * HDIM + idx] = newc;            // new_c
    out[idx] = o * tanhf(newc);                // new_g
}

// ---------------- launch -----------------------------------------------------------
extern "C" void kernel_launch(void* const* d_in, const int* in_sizes, int n_in,
                              void* d_out, int out_size)
{
    const float* g   = (const float*)d_in[0];
    const float* c_g = (const float*)d_in[1];
    const float* h   = (const float*)d_in[2];
    const float* c   = (const float*)d_in[3];
    const float* W_w = (const float*)d_in[4];
    const float* w_w = (const float*)d_in[5];
    const float* U_w = (const float*)d_in[6];
    const float* U_b = (const float*)d_in[7];
    const float* u_w = (const float*)d_in[8];
    const float* u_b = (const float*)d_in[9];
    float* out = (float*)d_out;

    (void)in_sizes; (void)n_in; (void)out_size;

    k_prep<<<544, 256>>>(h, u_w);
    k_fo<<<dim3(12, 16), 256>>>(g, W_w, U_w, w_w);

    static int smem_set = 0;
    if (!smem_set) {
        cudaFuncSetAttribute(k_main, cudaFuncAttributeMaxDynamicSharedMemorySize,
                             K3_SMEM_BYTES);
        smem_set = 1;
    }
    k_main<<<dim3(8, 2, 128), 256, K3_SMEM_BYTES>>>(c, u_b);
    k_comb<<<256, 256>>>(U_b, c_g, out);
}

// round 15
// speedup vs baseline: 1.1054x; 1.0264x over previous
#include <cuda_runtime.h>
#include <cuda_fp16.h>
#include <math.h>
#include <stdint.h>

#define BATCH 128
#define WDIM  512
#define HDIM  512
#define WH    (WDIM * HDIM)
#define NOUT  1536
#define K2_SPLITS 16
#define HPARTS 8

// ---------------- scratch (device globals: allocation-free rule) -------------
__device__ __align__(16) float  g_hpart[HPARTS * BATCH * HDIM];
__device__ __align__(16) float  g_part[K2_SPLITS * BATCH * NOUT];
__device__ __align__(16) float  g_red1[2 * BATCH * HDIM];
__device__ __align__(16) float  g_red2[2 * BATCH * HDIM];
__device__ __align__(16) __half g_h16[BATCH * WH];
__device__ __align__(16) __half g_uw16[HDIM * HDIM];

// ---------------- fast math ------------------------------------------------------
__device__ __forceinline__ float fast_exp(float x)
{
    float y = x * 1.44269504089f;
    y = fminf(fmaxf(y, -125.0f), 125.0f);
    float z = y + 12582912.0f;
    int   n = __float_as_int(z) - 0x4B400000;
    float f = y - (z - 12582912.0f);
    float t = f * 0.69314718056f;
    float p = 0.0013888889f;
    p = fmaf(p, t, 0.0083333333f);
    p = fmaf(p, t, 0.0416666667f);
    p = fmaf(p, t, 0.1666666667f);
    p = fmaf(p, t, 0.5f);
    p = fmaf(p, t, 1.0f);
    p = fmaf(p, t, 1.0f);
    return __int_as_float(__float_as_int(p) + (n << 23));
}
__device__ __forceinline__ float fast_rcp(float d)
{
    float r = __int_as_float(0x7EF311C3 - __float_as_int(d));
    r = r * (2.0f - d * r);
    r = r * (2.0f - d * r);
    r = r * (2.0f - d * r);
    return r;
}
__device__ __forceinline__ float tanh_mufu(float x)
{
    float r;
    asm("tanh.approx.f32 %0, %1;" : "=f"(r) : "f"(x));
    return r;
}
__device__ __forceinline__ float ex2_mufu(float x)
{
    float r;
    asm("ex2.approx.f32 %0, %1;" : "=f"(r) : "f"(x));
    return r;
}

// ---------------- mma / ldmatrix / cp.async helpers ------------------------------
__device__ __forceinline__ void mma_f16(float* d, const uint32_t* a, const uint32_t* b)
{
    asm volatile(
        "mma.sync.aligned.m16n8k16.row.col.f32.f16.f16.f32 "
        "{%0,%1,%2,%3}, {%4,%5,%6,%7}, {%8,%9}, {%0,%1,%2,%3};"
        : "+f"(d[0]), "+f"(d[1]), "+f"(d[2]), "+f"(d[3])
        : "r"(a[0]), "r"(a[1]), "r"(a[2]), "r"(a[3]),
          "r"(b[0]), "r"(b[1]));
}
__device__ __forceinline__ void ldsm_x4(uint32_t* r, uint32_t addr)
{
    asm volatile("ldmatrix.sync.aligned.m8n8.x4.shared.b16 {%0,%1,%2,%3}, [%4];"
                 : "=r"(r[0]), "=r"(r[1]), "=r"(r[2]), "=r"(r[3]) : "r"(addr));
}
__device__ __forceinline__ void cp16(uint32_t saddr, const void* g)
{
    asm volatile("cp.async.cg.shared.global [%0], [%1], 16;" :: "r"(saddr), "l"(g));
}
__device__ __forceinline__ void cp_commit()
{
    asm volatile("cp.async.commit_group;" ::: "memory");
}
template<int N> __device__ __forceinline__ void cp_wait()
{
    asm volatile("cp.async.wait_group %0;" :: "n"(N) : "memory");
}

// ---------------- GEMM inner body shared by both fo kernels -----------------------
// Computes a 128(b) x 128(j) tile over one 64-wide K slice, given a staged A loader.
template<bool HI>
__device__ __forceinline__ void fo_gemm_body(
    float* As, float* Bs, int nt, int ks, int tid,
    const float* __restrict__ g, const float* __restrict__ W_w,
    const float* __restrict__ U_w, const float* __restrict__ w_w)
{
    int tx = tid & 15;
    int ty = tid >> 4;

    float acc[8][8];
#pragma unroll
    for (int r = 0; r < 8; ++r)
#pragma unroll
        for (int s = 0; s < 8; ++s) acc[r][s] = 0.f;

    const int kbase = (HI ? (ks - 8) : ks) * 64;   // local offset within half
    const int q  = tid & 3;
    const int lr = tid >> 2;

    for (int kk = 0; kk < 64; kk += 16) {
#pragma unroll
        for (int p = 0; p < 2; ++p) {
            int b  = p * 64 + lr;
            int ko = kbase + kk + q * 4;           // 0..511 within half
            float4 v;
            if (!HI) {
                v = *(const float4*)(g + b * 512 + ko);
            } else {
                float4 a4 = make_float4(0.f, 0.f, 0.f, 0.f);
#pragma unroll
                for (int s = 0; s < HPARTS; ++s) {
                    float4 t = *(const float4*)&g_hpart[(s * BATCH + b) * HDIM + ko];
                    a4.x += t.x; a4.y += t.y; a4.z += t.z; a4.w += t.w;
                }
                const float inv = 1.0f / 512.0f;
                v = make_float4(a4.x * inv, a4.y * inv, a4.z * inv, a4.w * inv);
            }
            float* dst = &As[(q * 4) * 132 + b];
            dst[0] = v.x; dst[132] = v.y; dst[2*132] = v.z; dst[3*132] = v.w;
        }
#pragma unroll
        for (int p = 0; p < 2; ++p) {
            int jj = p * 64 + lr;
            int j  = nt * 128 + jj;
            int ko = kbase + kk + q * 4;
            float4 v;
            if (!HI) {
                // kg = ko < 512
                if (j < 1024) v = *(const float4*)(W_w + j * 512 + ko);
                else          v = *(const float4*)(w_w + (j - 1024) * 512 + ko);
            } else {
                // kg = 512 + ko
                if (j < 1024) v = *(const float4*)(U_w + j * 512 + ko);
                else          v = make_float4(0.f, 0.f, 0.f, 0.f);
            }
            float* dst = &Bs[(q * 4) * 132 + jj];
            dst[0] = v.x; dst[132] = v.y; dst[2*132] = v.z; dst[3*132] = v.w;
        }
        __syncthreads();

#pragma unroll
        for (int kc = 0; kc < 16; ++kc) {
            float4 a0 = *(const float4*)&As[kc * 132 + ty * 8];
            float4 a1 = *(const float4*)&As[kc * 132 + ty * 8 + 4];
            float4 b0 = *(const float4*)&Bs[kc * 132 + tx * 8];
            float4 b1 = *(const float4*)&Bs[kc * 132 + tx * 8 + 4];
            float av[8] = {a0.x, a0.y, a0.z, a0.w, a1.x, a1.y, a1.z, a1.w};
            float bv[8] = {b0.x, b0.y, b0.z, b0.w, b1.x, b1.y, b1.z, b1.w};
#pragma unroll
            for (int r = 0; r < 8; ++r)
#pragma unroll
                for (int s = 0; s < 8; ++s) acc[r][s] += av[r] * bv[s];
        }
        __syncthreads();
    }

#pragma unroll
    for (int r = 0; r < 8; ++r) {
        int bb = ty * 8 + r;
        float* dst = &g_part[(ks * 128 + bb) * NOUT + nt * 128 + tx * 8];
        *(float4*)dst       = make_float4(acc[r][0], acc[r][1], acc[r][2], acc[r][3]);
        *(float4*)(dst + 4) = make_float4(acc[r][4], acc[r][5], acc[r][6], acc[r][7]);
    }
}

// ---------------- K0: fused — fo-GEMM lo-half (no deps) + h prep + u_w conv -------
// Blocks [0,96): fo GEMM K-splits 0..7 (g only). [96,608): h slices. [608,640): u_w.
__global__ void __launch_bounds__(256)
k_fused(const float* __restrict__ h, const float* __restrict__ u_w,
        const float* __restrict__ g, const float* __restrict__ W_w,
        const float* __restrict__ U_w, const float* __restrict__ w_w)
{
    __shared__ __align__(16) float As[16 * 132];
    __shared__ __align__(16) float Bs[16 * 132];

    int gb  = blockIdx.x;
    int tid = threadIdx.x;

    if (gb < 96) {
        int nt = gb % 12;
        int ks = gb / 12;                 // 0..7  -> kg < 512, g only
        fo_gemm_body<false>(As, Bs, nt, ks, tid, g, W_w, U_w, w_w);
    } else if (gb < 608) {
        int gb2 = gb - 96;
        int b  = gb2 >> 2;
        int ws = gb2 & 3;                 // 128-row slice
        int tq = tid & 127;               // float4 column
        int th = tid >> 7;                // 0/1 -> 64-row half
        const float4* p = (const float4*)(h + (size_t)b * WH +
                                          ((size_t)ws * 128 + th * 64) * HDIM) + tq;
        uint2* q = (uint2*)(g_h16 + (size_t)b * WH +
                            ((size_t)ws * 128 + th * 64) * HDIM) + tq;
        float4 s = make_float4(0.f, 0.f, 0.f, 0.f);
#pragma unroll 8
        for (int w = 0; w < 64; ++w) {
            float4 v = p[(size_t)w * (HDIM / 4)];
            s.x += v.x; s.y += v.y; s.z += v.z; s.w += v.w;
            __half2 h0 = __floats2half2_rn(v.x, v.y);
            __half2 h1 = __floats2half2_rn(v.z, v.w);
            uint2 uu;
            uu.x = *reinterpret_cast<const uint32_t*>(&h0);
            uu.y = *reinterpret_cast<const uint32_t*>(&h1);
            q[(size_t)w * (HDIM / 4)] = uu;
        }
        int ws2 = ws * 2 + th;            // 8 partials of 64 rows each
        *(float4*)&g_hpart[(ws2 * BATCH + b) * HDIM + tq * 4] = s;
    } else {
        int t = (gb - 608) * 256 + tid;          // 0..8191
#pragma unroll
        for (int i = 0; i < 8; ++i) {
            int idx = t + i * 8192;              // float4 index, 65536 total
            float4 v = ((const float4*)u_w)[idx];
            ((__half2*)g_uw16)[idx * 2]     = __floats2half2_rn(v.x, v.y);
            ((__half2*)g_uw16)[idx * 2 + 1] = __floats2half2_rn(v.z, v.w);
        }
    }
}

// ---------------- K2: fo GEMM hi-half (K splits 8..15, needs g_hpart) -------------
__global__ void __launch_bounds__(256)
k_fo_hi(const float* __restrict__ g, const float* __restrict__ W_w,
        const float* __restrict__ U_w, const float* __restrict__ w_w)
{
    __shared__ __align__(16) float As[16 * 132];
    __shared__ __align__(16) float Bs[16 * 132];
    fo_gemm_body<true>(As, Bs, blockIdx.x, 8 + blockIdx.y, (int)threadIdx.x,
                       g, W_w, U_w, w_w);
}

// ---------------- K3: fp16 mma (R8 config); 'a' reduction fused into prologue -----
// CTA = (64-col H tile, 256-row W slice, batch). 256 threads, 8 warps, 2 CTAs/SM.
#define KCH     64
#define NCHUNK  8
#define OFF_ADD_F  0               // 64 floats
#define OFF_R1_F   64
#define OFF_R2_F   576
#define SM_STAGE_B 4608            // stages: A 32KB + B 8KB, x2
#define A_BYTES    32768
#define STAGE_BYTES 40960
#define S2_STRIDE  33
#define K3_SMEM_BYTES (SM_STAGE_B + 2 * STAGE_BYTES)   // 86528

__global__ void __launch_bounds__(256, 2)
k_main(const float* __restrict__ c, const float* __restrict__ u_b)
{
    extern __shared__ __align__(128) float sm[];
    const uint32_t smb = (uint32_t)__cvta_generic_to_shared(sm);

    const int ht0  = blockIdx.x * 64;
    const int ws   = blockIdx.y;      // 0/1 : 256-row W slice
    const int b    = blockIdx.z;
    const int tid  = threadIdx.x;
    const int wid  = tid >> 5;
    const int lane = tid & 31;
    const int wm   = wid >> 1;        // 0..3
    const int wn   = wid & 1;         // 0..1
    const int g4   = lane >> 2;
    const int t4   = lane & 3;

    const __half* hbs = g_h16 + (size_t)b * WH + (size_t)ws * 256 * HDIM;

    // fused 'a' reduction: a[col] = sum over K2 splits + u_b (consumed at epilogue)
    if (tid < 64) {
        float a = u_b[ht0 + tid];
#pragma unroll
        for (int ks = 0; ks < K2_SPLITS; ++ks)
            a += g_part[(ks * 128 + b) * NOUT + 1024 + ht0 + tid];
        sm[OFF_ADD_F + tid] = a;
    }

    // ---- cp.async staging ----
    const int crow = tid >> 3;        // 0..31
    const int aq   = tid & 7;
    const int brow = tid >> 2;        // 0..63
    const int bq0  = (tid & 3) * 2;

    auto load_chunk = [&](int ch, int st) {
        const uint32_t sa = smb + SM_STAGE_B + (uint32_t)st * STAGE_BYTES;
        const __half* gA = hbs + ch * KCH + aq * 8;
#pragma unroll
        for (int p = 0; p < 8; ++p) {
            int row = crow + p * 32;
            cp16(sa + (uint32_t)(row * 128 + ((aq ^ (row & 7)) << 4)),
                 gA + (size_t)row * HDIM);
        }
        const uint32_t sb = sa + A_BYTES;
        const __half* gB = g_uw16 + (size_t)(ht0 + brow) * HDIM + ch * KCH;
#pragma unroll
        for (int i = 0; i < 2; ++i) {
            int q = bq0 + i;
            cp16(sb + (uint32_t)(brow * 128 + ((q ^ (brow & 7)) << 4)), gB + q * 8);
        }
        cp_commit();
    };

    // ---- ldmatrix per-lane bases ----
    const int lane15 = lane & 15;
    const int laneQA = lane >> 4;
    const int laneQB = (lane >> 3) & 1;

    uint32_t aBase[4], aRL[4];
#pragma unroll
    for (int tm = 0; tm < 4; ++tm) {
        int row = wm * 64 + tm * 16 + lane15;
        aRL[tm]   = row & 7;
        aBase[tm] = smb + SM_STAGE_B + (uint32_t)(row * 128);
    }
    uint32_t bBase[2], bRL[2];
#pragma unroll
    for (int p = 0; p < 2; ++p) {
        int row = wn * 32 + p * 16 + ((lane >> 4) << 3) + (lane & 7);
        bRL[p]   = row & 7;
        bBase[p] = smb + SM_STAGE_B + A_BYTES + (uint32_t)(row * 128);
    }

    float acc[4][4][4];
#pragma unroll
    for (int i = 0; i < 4; ++i)
#pragma unroll
        for (int j = 0; j < 4; ++j)
#pragma unroll
            for (int r = 0; r < 4; ++r) acc[i][j][r] = 0.f;

    // ---- 2-stage pipeline (R8 proven config) ----
    load_chunk(0, 0);
    load_chunk(1, 1);

    for (int ch = 0; ch < NCHUNK; ++ch) {
        const int st = ch & 1;
        if (ch == NCHUNK - 1) cp_wait<0>(); else cp_wait<1>();
        __syncthreads();

        const uint32_t off = (uint32_t)st * STAGE_BYTES;
#pragma unroll
        for (int ks = 0; ks < 4; ++ks) {
            const uint32_t qb = (uint32_t)(ks * 2);
            uint32_t af[4][4], bf[4][2];
#pragma unroll
            for (int tm = 0; tm < 4; ++tm)
                ldsm_x4(af[tm], aBase[tm] + off + (((qb + laneQA) ^ aRL[tm]) << 4));
#pragma unroll
            for (int p = 0; p < 2; ++p) {
                uint32_t tmp[4];
                ldsm_x4(tmp, bBase[p] + off + (((qb + laneQB) ^ bRL[p]) << 4));
                bf[2 * p][0] = tmp[0];     bf[2 * p][1] = tmp[1];
                bf[2 * p + 1][0] = tmp[2]; bf[2 * p + 1][1] = tmp[3];
            }
#pragma unroll
            for (int tm = 0; tm < 4; ++tm)
#pragma unroll
                for (int tn = 0; tn < 4; ++tn)
                    mma_f16(acc[tm][tn], af[tm], bf[tn]);
        }
        __syncthreads();
        if (ch + 2 < NCHUNK) load_chunk(ch + 2, st);
    }

    // ---- epilogue: exp(sigmoid(x)) ∝ exp2(K*tanh(x/2)); sqrt(e) cancels ----------
    __half2* S2 = (__half2*)(sm + SM_STAGE_B / 4);   // 256 x 33 half2, aliases stages
    const float KE = 0.72134752f;     // 0.5 * log2(e)
#pragma unroll
    for (int tm = 0; tm < 4; ++tm) {
#pragma unroll
        for (int tn = 0; tn < 4; ++tn) {
            int colb = wn * 32 + tn * 8 + t4 * 2;
            float add0 = sm[OFF_ADD_F + colb];
            float add1 = sm[OFF_ADD_F + colb + 1];
#pragma unroll
            for (int r = 0; r < 2; ++r) {
                int w = wm * 64 + tm * 16 + g4 + r * 8;
                float x0 = acc[tm][tn][r * 2 + 0] + add0;
                float x1 = acc[tm][tn][r * 2 + 1] + add1;
                float s0 = ex2_mufu(KE * tanh_mufu(0.5f * x0));
                float s1 = ex2_mufu(KE * tanh_mufu(0.5f * x1));
                S2[w * S2_STRIDE + (colb >> 1)] = __floats2half2_rn(s0, s1);
            }
        }
    }
    __syncthreads();

    // ---- partial softmax denominator + weighted-c numerator over 256 rows --------
    const int colp = tid & 31;
    const int seg  = tid >> 5;        // 8 segments x 32 w
    const float* cbase = c + (size_t)b * WH + (size_t)ws * 256 * HDIM
                       + ht0 + colp * 2;
    float dsx = 0.f, dsy = 0.f, wsx = 0.f, wsy = 0.f;
#pragma unroll 4
    for (int ww = 0; ww < 32; ++ww) {
        int w = seg * 32 + ww;
        float2 e  = __half22float2(S2[w * S2_STRIDE + colp]);
        float2 cv = __ldcg((const float2*)(cbase + (size_t)w * HDIM));
        dsx += e.x; dsy += e.y;
        wsx += e.x * cv.x; wsy += e.y * cv.y;
    }
    __syncthreads();
    *(float2*)&sm[OFF_R1_F + seg * 64 + colp * 2] = make_float2(dsx, dsy);
    *(float2*)&sm[OFF_R2_F + seg * 64 + colp * 2] = make_float2(wsx, wsy);
    __syncthreads();

    if (tid < 64) {
        float dt = 0.f, wt = 0.f;
#pragma unroll
        for (int s2 = 0; s2 < 8; ++s2) {
            dt += sm[OFF_R1_F + s2 * 64 + tid];
            wt += sm[OFF_R2_F + s2 * 64 + tid];
        }
        int gi = (ws * BATCH + b) * HDIM + ht0 + tid;
        g_red1[gi] = dt;
        g_red2[gi] = wt;
    }
}

// ---------------- K4: paired-thread combine + f/o sigmoid -> outputs --------------
__global__ void k_comb(const float* __restrict__ U_b, const float* __restrict__ c_g,
                       float* __restrict__ out)
{
    int t = blockIdx.x * blockDim.x + threadIdx.x;     // 0..131071
    int e = t >> 1;                                    // element 0..65535
    int role = t & 1;                                  // 0: f, 1: o
    int b = e >> 9;
    int j = e & 511;
    int jr = j + role * 512;

    float s = 0.f;
#pragma unroll
    for (int ks = 0; ks < K2_SPLITS; ++ks)
        s += g_part[(ks * 128 + b) * NOUT + jr];
    float v = fast_rcp(1.f + fast_exp(-(s + U_b[jr])));
    float other = __shfl_xor_sync(0xFFFFFFFFu, v, 1);

    float f = role ? other : v;
    float o = role ? v : other;

    float dt = g_red1[e] + g_red1[BATCH * HDIM + e];
    float wt = g_red2[e] + g_red2[BATCH * HDIM + e];
    float newc = f * c_g[e] + wt / dt;
    if (role) out[BATCH * HDIM + e] = newc;            // new_c
    else      out[e] = o * tanhf(newc);                // new_g
}

// ---------------- launch -----------------------------------------------------------
extern "C" void kernel_launch(void* const* d_in, const int* in_sizes, int n_in,
                              void* d_out, int out_size)
{
    const float* g   = (const float*)d_in[0];
    const float* c_g = (const float*)d_in[1];
    const float* h   = (const float*)d_in[2];
    const float* c   = (const float*)d_in[3];
    const float* W_w = (const float*)d_in[4];
    const float* w_w = (const float*)d_in[5];
    const float* U_w = (const float*)d_in[6];
    const float* U_b = (const float*)d_in[7];
    const float* u_w = (const float*)d_in[8];
    const float* u_b = (const float*)d_in[9];
    float* out = (float*)d_out;

    (void)in_sizes; (void)n_in; (void)out_size;

    k_fused<<<640, 256>>>(h, u_w, g, W_w, U_w, w_w);   // fo lo-half + h prep + u_w
    k_fo_hi<<<dim3(12, 8), 256>>>(g, W_w, U_w, w_w);   // fo hi-half (needs hpart)

    static int smem_set = 0;
    if (!smem_set) {
        cudaFuncSetAttribute(k_main, cudaFuncAttributeMaxDynamicSharedMemorySize,
                             K3_SMEM_BYTES);
        smem_set = 1;
    }
    k_main<<<dim3(8, 2, 128), 256, K3_SMEM_BYTES>>>(c, u_b);
    k_comb<<<512, 256>>>(U_b, c_g, out);
}

// round 16
// speedup vs baseline: 1.2165x; 1.1005x over previous
#include <cuda_runtime.h>
#include <cuda_fp16.h>
#include <math.h>
#include <stdint.h>

#define BATCH 128
#define WDIM  512
#define HDIM  512
#define WH    (WDIM * HDIM)
#define NOUT  1536
#define K2S   8               // 8 splits total: 0..3 lo (g), 4..7 hi (h_avg)
#define HPARTS 8

// ---------------- scratch (device globals: allocation-free rule) -------------
__device__ __align__(16) float  g_hpart[HPARTS * BATCH * HDIM];
__device__ __align__(16) float  g_part[K2S * BATCH * NOUT];
__device__ __align__(16) float  g_red1[2 * BATCH * HDIM];
__device__ __align__(16) float  g_red2[2 * BATCH * HDIM];
__device__ __align__(16) __half g_h16[BATCH * WH];
__device__ __align__(16) __half g_uw16[HDIM * HDIM];

// ---------------- fast math ------------------------------------------------------
__device__ __forceinline__ float fast_exp(float x)
{
    float y = x * 1.44269504089f;
    y = fminf(fmaxf(y, -125.0f), 125.0f);
    float z = y + 12582912.0f;
    int   n = __float_as_int(z) - 0x4B400000;
    float f = y - (z - 12582912.0f);
    float t = f * 0.69314718056f;
    float p = 0.0013888889f;
    p = fmaf(p, t, 0.0083333333f);
    p = fmaf(p, t, 0.0416666667f);
    p = fmaf(p, t, 0.1666666667f);
    p = fmaf(p, t, 0.5f);
    p = fmaf(p, t, 1.0f);
    p = fmaf(p, t, 1.0f);
    return __int_as_float(__float_as_int(p) + (n << 23));
}
__device__ __forceinline__ float fast_rcp(float d)
{
    float r = __int_as_float(0x7EF311C3 - __float_as_int(d));
    r = r * (2.0f - d * r);
    r = r * (2.0f - d * r);
    r = r * (2.0f - d * r);
    return r;
}
__device__ __forceinline__ float tanh_mufu(float x)
{
    float r;
    asm("tanh.approx.f32 %0, %1;" : "=f"(r) : "f"(x));
    return r;
}
__device__ __forceinline__ float ex2_mufu(float x)
{
    float r;
    asm("ex2.approx.f32 %0, %1;" : "=f"(r) : "f"(x));
    return r;
}

// ---------------- mma / ldmatrix / cp.async helpers ------------------------------
__device__ __forceinline__ void mma_f16(float* d, const uint32_t* a, const uint32_t* b)
{
    asm volatile(
        "mma.sync.aligned.m16n8k16.row.col.f32.f16.f16.f32 "
        "{%0,%1,%2,%3}, {%4,%5,%6,%7}, {%8,%9}, {%0,%1,%2,%3};"
        : "+f"(d[0]), "+f"(d[1]), "+f"(d[2]), "+f"(d[3])
        : "r"(a[0]), "r"(a[1]), "r"(a[2]), "r"(a[3]),
          "r"(b[0]), "r"(b[1]));
}
__device__ __forceinline__ void ldsm_x4(uint32_t* r, uint32_t addr)
{
    asm volatile("ldmatrix.sync.aligned.m8n8.x4.shared.b16 {%0,%1,%2,%3}, [%4];"
                 : "=r"(r[0]), "=r"(r[1]), "=r"(r[2]), "=r"(r[3]) : "r"(addr));
}
__device__ __forceinline__ void cp16(uint32_t saddr, const void* g)
{
    asm volatile("cp.async.cg.shared.global [%0], [%1], 16;" :: "r"(saddr), "l"(g));
}
__device__ __forceinline__ void cp_commit()
{
    asm volatile("cp.async.commit_group;" ::: "memory");
}
template<int N> __device__ __forceinline__ void cp_wait()
{
    asm volatile("cp.async.wait_group %0;" :: "n"(N) : "memory");
}

// ---------------- GEMM body: 128(b) x 128(j) tile over one 128-wide K slice -------
// ksg in [0,8): 0..3 = lo half (A from g), 4..7 = hi half (A from h_avg partials).
__device__ __forceinline__ void fo_gemm_body(
    float* As, float* Bs, int nt, int ksg, int tid,
    const float* __restrict__ g, const float* __restrict__ W_w,
    const float* __restrict__ U_w, const float* __restrict__ w_w)
{
    const bool hi = (ksg >= 4);
    int tx = tid & 15;
    int ty = tid >> 4;

    float acc[8][8];
#pragma unroll
    for (int r = 0; r < 8; ++r)
#pragma unroll
        for (int s = 0; s < 8; ++s) acc[r][s] = 0.f;

    const int kbase = (ksg & 3) * 128;           // local offset within half
    const int q  = tid & 3;
    const int lr = tid >> 2;

    for (int kk = 0; kk < 128; kk += 16) {
#pragma unroll
        for (int p = 0; p < 2; ++p) {
            int b  = p * 64 + lr;
            int ko = kbase + kk + q * 4;         // 0..511 within half
            float4 v;
            if (!hi) {
                v = *(const float4*)(g + b * 512 + ko);
            } else {
                float4 a4 = make_float4(0.f, 0.f, 0.f, 0.f);
#pragma unroll
                for (int s = 0; s < HPARTS; ++s) {
                    float4 t = *(const float4*)&g_hpart[(s * BATCH + b) * HDIM + ko];
                    a4.x += t.x; a4.y += t.y; a4.z += t.z; a4.w += t.w;
                }
                const float inv = 1.0f / 512.0f;
                v = make_float4(a4.x * inv, a4.y * inv, a4.z * inv, a4.w * inv);
            }
            float* dst = &As[(q * 4) * 132 + b];
            dst[0] = v.x; dst[132] = v.y; dst[2*132] = v.z; dst[3*132] = v.w;
        }
#pragma unroll
        for (int p = 0; p < 2; ++p) {
            int jj = p * 64 + lr;
            int j  = nt * 128 + jj;
            int ko = kbase + kk + q * 4;
            float4 v;
            if (!hi) {
                if (j < 1024) v = *(const float4*)(W_w + j * 512 + ko);
                else          v = *(const float4*)(w_w + (j - 1024) * 512 + ko);
            } else {
                // hi blocks are launched only with nt < 8 (j < 1024)
                v = *(const float4*)(U_w + j * 512 + ko);
            }
            float* dst = &Bs[(q * 4) * 132 + jj];
            dst[0] = v.x; dst[132] = v.y; dst[2*132] = v.z; dst[3*132] = v.w;
        }
        __syncthreads();

#pragma unroll
        for (int kc = 0; kc < 16; ++kc) {
            float4 a0 = *(const float4*)&As[kc * 132 + ty * 8];
            float4 a1 = *(const float4*)&As[kc * 132 + ty * 8 + 4];
            float4 b0 = *(const float4*)&Bs[kc * 132 + tx * 8];
            float4 b1 = *(const float4*)&Bs[kc * 132 + tx * 8 + 4];
            float av[8] = {a0.x, a0.y, a0.z, a0.w, a1.x, a1.y, a1.z, a1.w};
            float bv[8] = {b0.x, b0.y, b0.z, b0.w, b1.x, b1.y, b1.z, b1.w};
#pragma unroll
            for (int r = 0; r < 8; ++r)
#pragma unroll
                for (int s = 0; s < 8; ++s) acc[r][s] += av[r] * bv[s];
        }
        __syncthreads();
    }

#pragma unroll
    for (int r = 0; r < 8; ++r) {
        int bb = ty * 8 + r;
        float* dst = &g_part[(ksg * 128 + bb) * NOUT + nt * 128 + tx * 8];
        *(float4*)dst       = make_float4(acc[r][0], acc[r][1], acc[r][2], acc[r][3]);
        *(float4*)(dst + 4) = make_float4(acc[r][4], acc[r][5], acc[r][6], acc[r][7]);
    }
}

// ---------------- K0: fused — fo-GEMM lo-half + h prep + u_w conv -----------------
// Blocks [0,48): GEMM splits 0..3. [48,560): h slices. [560,592): u_w.
__global__ void __launch_bounds__(256)
k_fused(const float* __restrict__ h, const float* __restrict__ u_w,
        const float* __restrict__ g, const float* __restrict__ W_w,
        const float* __restrict__ U_w, const float* __restrict__ w_w)
{
    __shared__ __align__(16) float As[16 * 132];
    __shared__ __align__(16) float Bs[16 * 132];

    int gb  = blockIdx.x;
    int tid = threadIdx.x;

    if (gb < 48) {
        int nt = gb % 12;
        int ks = gb / 12;                 // 0..3 (lo half, g only)
        fo_gemm_body(As, Bs, nt, ks, tid, g, W_w, U_w, w_w);
    } else if (gb < 560) {
        int gb2 = gb - 48;
        int b  = gb2 >> 2;
        int ws = gb2 & 3;                 // 128-row slice
        int tq = tid & 127;               // float4 column
        int th = tid >> 7;                // 0/1 -> 64-row half
        const float4* p = (const float4*)(h + (size_t)b * WH +
                                          ((size_t)ws * 128 + th * 64) * HDIM) + tq;
        uint2* q = (uint2*)(g_h16 + (size_t)b * WH +
                            ((size_t)ws * 128 + th * 64) * HDIM) + tq;
        float4 s = make_float4(0.f, 0.f, 0.f, 0.f);
#pragma unroll 8
        for (int w = 0; w < 64; ++w) {
            float4 v = p[(size_t)w * (HDIM / 4)];
            s.x += v.x; s.y += v.y; s.z += v.z; s.w += v.w;
            __half2 h0 = __floats2half2_rn(v.x, v.y);
            __half2 h1 = __floats2half2_rn(v.z, v.w);
            uint2 uu;
            uu.x = *reinterpret_cast<const uint32_t*>(&h0);
            uu.y = *reinterpret_cast<const uint32_t*>(&h1);
            q[(size_t)w * (HDIM / 4)] = uu;
        }
        int ws2 = ws * 2 + th;            // 8 partials of 64 rows each
        *(float4*)&g_hpart[(ws2 * BATCH + b) * HDIM + tq * 4] = s;
    } else {
        int t = (gb - 560) * 256 + tid;          // 0..8191
#pragma unroll
        for (int i = 0; i < 8; ++i) {
            int idx = t + i * 8192;              // float4 index, 65536 total
            float4 v = ((const float4*)u_w)[idx];
            ((__half2*)g_uw16)[idx * 2]     = __floats2half2_rn(v.x, v.y);
            ((__half2*)g_uw16)[idx * 2 + 1] = __floats2half2_rn(v.z, v.w);
        }
    }
}

// ---------------- K3: unified — hi-GEMM blocks + fp16 mma main tiles --------------
// Blocks [0,32): hi-GEMM (nt 0..7, ks 4..7) using dynamic smem.
// Blocks [32,2080): main tile (ht, ws, b). 256 threads, 2 CTAs/SM.
#define KCH     64
#define NCHUNK  8
#define OFF_ADD_F  0               // 64 floats
#define OFF_R1_F   64
#define OFF_R2_F   576
#define SM_STAGE_B 4608            // stages: A 32KB + B 8KB, x2
#define A_BYTES    32768
#define STAGE_BYTES 40960
#define S2_STRIDE  33
#define K3_SMEM_BYTES (SM_STAGE_B + 2 * STAGE_BYTES)   // 86528

__global__ void __launch_bounds__(256, 2)
k_main(const float* __restrict__ c, const float* __restrict__ u_b,
       const float* __restrict__ g, const float* __restrict__ W_w,
       const float* __restrict__ U_w, const float* __restrict__ w_w)
{
    extern __shared__ __align__(128) float sm[];
    const uint32_t smb = (uint32_t)__cvta_generic_to_shared(sm);
    const int tid  = threadIdx.x;

    if (blockIdx.x < 32) {
        // hi-half fo GEMM: writes g_part splits 4..7 (j<1024); consumed by k_comb.
        int nt = blockIdx.x & 7;
        int ks = 4 + (blockIdx.x >> 3);
        fo_gemm_body(sm, sm + 16 * 132, nt, ks, tid, g, W_w, U_w, w_w);
        return;
    }

    const int idx  = blockIdx.x - 32;
    const int ht0  = (idx & 7) * 64;
    const int ws   = (idx >> 3) & 1;  // 0/1 : 256-row W slice
    const int b    = idx >> 4;
    const int wid  = tid >> 5;
    const int lane = tid & 31;
    const int wm   = wid >> 1;        // 0..3
    const int wn   = wid & 1;         // 0..1
    const int g4   = lane >> 2;
    const int t4   = lane & 3;

    const __half* hbs = g_h16 + (size_t)b * WH + (size_t)ws * 256 * HDIM;

    // fused 'a' reduction over LO splits only (hi contributes exact zeros)
    if (tid < 64) {
        float a = u_b[ht0 + tid];
#pragma unroll
        for (int ks = 0; ks < 4; ++ks)
            a += g_part[(ks * 128 + b) * NOUT + 1024 + ht0 + tid];
        sm[OFF_ADD_F + tid] = a;
    }

    // ---- cp.async staging ----
    const int crow = tid >> 3;        // 0..31
    const int aq   = tid & 7;
    const int brow = tid >> 2;        // 0..63
    const int bq0  = (tid & 3) * 2;

    auto load_chunk = [&](int ch, int st) {
        const uint32_t sa = smb + SM_STAGE_B + (uint32_t)st * STAGE_BYTES;
        const __half* gA = hbs + ch * KCH + aq * 8;
#pragma unroll
        for (int p = 0; p < 8; ++p) {
            int row = crow + p * 32;
            cp16(sa + (uint32_t)(row * 128 + ((aq ^ (row & 7)) << 4)),
                 gA + (size_t)row * HDIM);
        }
        const uint32_t sb = sa + A_BYTES;
        const __half* gB = g_uw16 + (size_t)(ht0 + brow) * HDIM + ch * KCH;
#pragma unroll
        for (int i = 0; i < 2; ++i) {
            int q = bq0 + i;
            cp16(sb + (uint32_t)(brow * 128 + ((q ^ (brow & 7)) << 4)), gB + q * 8);
        }
        cp_commit();
    };

    // ---- ldmatrix per-lane bases ----
    const int lane15 = lane & 15;
    const int laneQA = lane >> 4;
    const int laneQB = (lane >> 3) & 1;

    uint32_t aBase[4], aRL[4];
#pragma unroll
    for (int tm = 0; tm < 4; ++tm) {
        int row = wm * 64 + tm * 16 + lane15;
        aRL[tm]   = row & 7;
        aBase[tm] = smb + SM_STAGE_B + (uint32_t)(row * 128);
    }
    uint32_t bBase[2], bRL[2];
#pragma unroll
    for (int p = 0; p < 2; ++p) {
        int row = wn * 32 + p * 16 + ((lane >> 4) << 3) + (lane & 7);
        bRL[p]   = row & 7;
        bBase[p] = smb + SM_STAGE_B + A_BYTES + (uint32_t)(row * 128);
    }

    float acc[4][4][4];
#pragma unroll
    for (int i = 0; i < 4; ++i)
#pragma unroll
        for (int j = 0; j < 4; ++j)
#pragma unroll
            for (int r = 0; r < 4; ++r) acc[i][j][r] = 0.f;

    // ---- 2-stage pipeline (R8 proven config) ----
    load_chunk(0, 0);
    load_chunk(1, 1);

    for (int ch = 0; ch < NCHUNK; ++ch) {
        const int st = ch & 1;
        if (ch == NCHUNK - 1) cp_wait<0>(); else cp_wait<1>();
        __syncthreads();

        const uint32_t off = (uint32_t)st * STAGE_BYTES;
#pragma unroll
        for (int ks = 0; ks < 4; ++ks) {
            const uint32_t qb = (uint32_t)(ks * 2);
            uint32_t af[4][4], bf[4][2];
#pragma unroll
            for (int tm = 0; tm < 4; ++tm)
                ldsm_x4(af[tm], aBase[tm] + off + (((qb + laneQA) ^ aRL[tm]) << 4));
#pragma unroll
            for (int p = 0; p < 2; ++p) {
                uint32_t tmp[4];
                ldsm_x4(tmp, bBase[p] + off + (((qb + laneQB) ^ bRL[p]) << 4));
                bf[2 * p][0] = tmp[0];     bf[2 * p][1] = tmp[1];
                bf[2 * p + 1][0] = tmp[2]; bf[2 * p + 1][1] = tmp[3];
            }
#pragma unroll
            for (int tm = 0; tm < 4; ++tm)
#pragma unroll
                for (int tn = 0; tn < 4; ++tn)
                    mma_f16(acc[tm][tn], af[tm], bf[tn]);
        }
        __syncthreads();
        if (ch + 2 < NCHUNK) load_chunk(ch + 2, st);
    }

    // ---- epilogue: exp(sigmoid(x)) ∝ exp2(K*tanh(x/2)); sqrt(e) cancels ----------
    __half2* S2 = (__half2*)(sm + SM_STAGE_B / 4);   // 256 x 33 half2, aliases stages
    const float KE = 0.72134752f;     // 0.5 * log2(e)
#pragma unroll
    for (int tm = 0; tm < 4; ++tm) {
#pragma unroll
        for (int tn = 0; tn < 4; ++tn) {
            int colb = wn * 32 + tn * 8 + t4 * 2;
            float add0 = sm[OFF_ADD_F + colb];
            float add1 = sm[OFF_ADD_F + colb + 1];
#pragma unroll
            for (int r = 0; r < 2; ++r) {
                int w = wm * 64 + tm * 16 + g4 + r * 8;
                float x0 = acc[tm][tn][r * 2 + 0] + add0;
                float x1 = acc[tm][tn][r * 2 + 1] + add1;
                float s0 = ex2_mufu(KE * tanh_mufu(0.5f * x0));
                float s1 = ex2_mufu(KE * tanh_mufu(0.5f * x1));
                S2[w * S2_STRIDE + (colb >> 1)] = __floats2half2_rn(s0, s1);
            }
        }
    }
    __syncthreads();

    // ---- partial softmax denominator + weighted-c numerator over 256 rows --------
    const int colp = tid & 31;
    const int seg  = tid >> 5;        // 8 segments x 32 w
    const float* cbase = c + (size_t)b * WH + (size_t)ws * 256 * HDIM
                       + ht0 + colp * 2;
    float dsx = 0.f, dsy = 0.f, wsx = 0.f, wsy = 0.f;
#pragma unroll 4
    for (int ww = 0; ww < 32; ++ww) {
        int w = seg * 32 + ww;
        float2 e  = __half22float2(S2[w * S2_STRIDE + colp]);
        float2 cv = __ldcg((const float2*)(cbase + (size_t)w * HDIM));
        dsx += e.x; dsy += e.y;
        wsx += e.x * cv.x; wsy += e.y * cv.y;
    }
    __syncthreads();
    *(float2*)&sm[OFF_R1_F + seg * 64 + colp * 2] = make_float2(dsx, dsy);
    *(float2*)&sm[OFF_R2_F + seg * 64 + colp * 2] = make_float2(wsx, wsy);
    __syncthreads();

    if (tid < 64) {
        float dt = 0.f, wt = 0.f;
#pragma unroll
        for (int s2 = 0; s2 < 8; ++s2) {
            dt += sm[OFF_R1_F + s2 * 64 + tid];
            wt += sm[OFF_R2_F + s2 * 64 + tid];
        }
        int gi = (ws * BATCH + b) * HDIM + ht0 + tid;
        g_red1[gi] = dt;
        g_red2[gi] = wt;
    }
}

// ---------------- K4: paired-thread combine + f/o sigmoid -> outputs --------------
__global__ void k_comb(const float* __restrict__ U_b, const float* __restrict__ c_g,
                       float* __restrict__ out)
{
    int t = blockIdx.x * blockDim.x + threadIdx.x;     // 0..131071
    int e = t >> 1;                                    // element 0..65535
    int role = t & 1;                                  // 0: f, 1: o
    int b = e >> 9;
    int j = e & 511;
    int jr = j + role * 512;

    float s = 0.f;
#pragma unroll
    for (int ks = 0; ks < K2S; ++ks)
        s += g_part[(ks * 128 + b) * NOUT + jr];
    float v = fast_rcp(1.f + fast_exp(-(s + U_b[jr])));
    float other = __shfl_xor_sync(0xFFFFFFFFu, v, 1);

    float f = role ? other : v;
    float o = role ? v : other;

    float dt = g_red1[e] + g_red1[BATCH * HDIM + e];
    float wt = g_red2[e] + g_red2[BATCH * HDIM + e];
    float newc = f * c_g[e] + wt / dt;
    if (role) out[BATCH * HDIM + e] = newc;            // new_c
    else      out[e] = o * tanhf(newc);                // new_g
}

// ---------------- launch -----------------------------------------------------------
extern "C" void kernel_launch(void* const* d_in, const int* in_sizes, int n_in,
                              void* d_out, int out_size)
{
    const float* g   = (const float*)d_in[0];
    const float* c_g = (const float*)d_in[1];
    const float* h   = (const float*)d_in[2];
    const float* c   = (const float*)d_in[3];
    const float* W_w = (const float*)d_in[4];
    const float* w_w = (const float*)d_in[5];
    const float* U_w = (const float*)d_in[6];
    const float* U_b = (const float*)d_in[7];
    const float* u_w = (const float*)d_in[8];
    const float* u_b = (const float*)d_in[9];
    float* out = (float*)d_out;

    (void)in_sizes; (void)n_in; (void)out_size;

    k_fused<<<592, 256>>>(h, u_w, g, W_w, U_w, w_w);   // lo-GEMM + h prep + u_w

    static int smem_set = 0;
    if (!smem_set) {
        cudaFuncSetAttribute(k_main, cudaFuncAttributeMaxDynamicSharedMemorySize,
                             K3_SMEM_BYTES);
        smem_set = 1;
    }
    // 32 hi-GEMM blocks + 2048 main tiles
    k_main<<<2080, 256, K3_SMEM_BYTES>>>(c, u_b, g, W_w, U_w, w_w);
    k_comb<<<512, 256>>>(U_b, c_g, out);
}